// round 9
// baseline (speedup 1.0000x reference)
#include <cuda_runtime.h>
#include <cuda_bf16.h>
#include <cstdint>
#include <cstddef>

// ---------------------------------------------------------------------------
// Problem constants
// ---------------------------------------------------------------------------
namespace {
constexpr int B = 8, N = 4096, M = 4096, D = 128;
constexpr int BN = B * N;  // 32768 (== B*M)
constexpr int NSPLIT = 8;
constexpr float RATIO2 = 0.64f;  // 0.8^2
constexpr float DIST2  = 0.49f;  // 0.7^2

// GEMM smem layout: 4 operand tiles of 128 rows x (128 bf16 + 8 pad) = 272B/row
constexpr int ROWB   = 272;                 // padded row bytes (17 * 16B)
constexpr int TILEB  = 128 * ROWB;          // 34816 B per operand tile
constexpr int SA_H = 0;
constexpr int SA_L = TILEB;
constexpr int SB_H = 2 * TILEB;
constexpr int SB_L = 3 * TILEB;
constexpr int SMEM_BYTES = 4 * TILEB;       // 139264
}  // namespace

// ---------------------------------------------------------------------------
// Device scratch (no allocations allowed)
// ---------------------------------------------------------------------------
__device__ __nv_bfloat16 g_ah[(size_t)B * N * D];
__device__ __nv_bfloat16 g_al[(size_t)B * N * D];
__device__ __nv_bfloat16 g_bh[(size_t)B * M * D];
__device__ __nv_bfloat16 g_bl[(size_t)B * M * D];

struct alignas(16) Top2 { float v1, v2; int i1, i2; };
__device__ Top2 g_colpart[(size_t)B * NSPLIT * M];
__device__ int  g_m0[B * N];
__device__ int  g_m1[B * M];

// ---------------------------------------------------------------------------
// PTX helpers (portable: sm_80+ instructions only, safe at target sm_103)
// ---------------------------------------------------------------------------
__device__ __forceinline__ uint32_t smem_u32(const void* p) {
    uint32_t a;
    asm("{ .reg .u64 t; cvta.to.shared.u64 t, %1; cvt.u32.u64 %0, t; }" : "=r"(a) : "l"(p));
    return a;
}

__device__ __forceinline__ void ldmatrix_x4(uint32_t (&r)[4], uint32_t addr) {
    asm volatile("ldmatrix.sync.aligned.m8n8.x4.shared.b16 {%0,%1,%2,%3}, [%4];"
                 : "=r"(r[0]), "=r"(r[1]), "=r"(r[2]), "=r"(r[3]) : "r"(addr));
}

__device__ __forceinline__ void mma_16816(float (&d)[4], const uint32_t (&a)[4],
                                          const uint32_t* b) {
    asm volatile(
        "mma.sync.aligned.m16n8k16.row.col.f32.bf16.bf16.f32 "
        "{%0,%1,%2,%3}, {%4,%5,%6,%7}, {%8,%9}, {%0,%1,%2,%3};"
        : "+f"(d[0]), "+f"(d[1]), "+f"(d[2]), "+f"(d[3])
        : "r"(a[0]), "r"(a[1]), "r"(a[2]), "r"(a[3]), "r"(b[0]), "r"(b[1]));
}

// ---------------------------------------------------------------------------
// Top-2 helpers (lax.top_k semantics: larger wins; tie -> lower index)
// ---------------------------------------------------------------------------
__device__ __forceinline__ void t2_init(Top2& t) {
    t.v1 = -2e30f; t.v2 = -2e30f; t.i1 = 0x7fffffff; t.i2 = 0x7fffffff;
}
__device__ __forceinline__ void t2_push(Top2& t, float v, int i) {
    if (v > t.v1 || (v == t.v1 && i < t.i1)) {
        t.v2 = t.v1; t.i2 = t.i1; t.v1 = v; t.i1 = i;
    } else if (v > t.v2 || (v == t.v2 && i < t.i2)) {
        t.v2 = v; t.i2 = i;
    }
}
__device__ __forceinline__ void t2_merge(Top2& a, const Top2& b) {
    t2_push(a, b.v1, b.i1);
    t2_push(a, b.v2, b.i2);
}
__device__ __forceinline__ int t2_match(const Top2& t) {
    float d0 = 2.0f * (1.0f - t.v1);
    float d1 = 2.0f * (1.0f - t.v2);
    bool ok = (d0 <= RATIO2 * d1) && (d0 <= DIST2);
    return ok ? t.i1 : -1;
}

// ---------------------------------------------------------------------------
// Kernel 1: l2-normalize rows, split fp32 -> bf16 hi + bf16 lo
// ---------------------------------------------------------------------------
__global__ void norm_split_kernel(const float* __restrict__ d0, const float* __restrict__ d1) {
    int row  = blockIdx.x * 8 + (threadIdx.x >> 5);
    int lane = threadIdx.x & 31;

    const float* src;
    __nv_bfloat16 *ph, *pl;
    if (row < B * N) {
        src = d0 + (size_t)row * D;
        ph = g_ah + (size_t)row * D;
        pl = g_al + (size_t)row * D;
    } else {
        int r = row - B * N;
        src = d1 + (size_t)r * D;
        ph = g_bh + (size_t)r * D;
        pl = g_bl + (size_t)r * D;
    }
    float4 x = reinterpret_cast<const float4*>(src)[lane];
    float s = x.x * x.x + x.y * x.y + x.z * x.z + x.w * x.w;
#pragma unroll
    for (int o = 16; o > 0; o >>= 1) s += __shfl_xor_sync(0xffffffffu, s, o);
    float nrm = fmaxf(sqrtf(s), 1e-12f);

    float y[4] = {x.x / nrm, x.y / nrm, x.z / nrm, x.w / nrm};
#pragma unroll
    for (int i = 0; i < 4; ++i) {
        __nv_bfloat16 h = __float2bfloat16(y[i]);
        __nv_bfloat16 l = __float2bfloat16(y[i] - __bfloat162float(h));
        ph[lane * 4 + i] = h;
        pl[lane * 4 + i] = l;
    }
}

// ---------------------------------------------------------------------------
// Kernel 2: bf16 mma.sync GEMM  sim[b, r0:r0+128, c0:c0+128] = A @ B^T
//           split-bf16: AhBh + AhBl + AlBh, fp32 accumulation
//           CTA 128x128, 8 warps of 32x64, K=128 fully smem-resident
// ---------------------------------------------------------------------------
__global__ void __launch_bounds__(256, 1) sim_gemm_kernel(float* __restrict__ sim) {
    extern __shared__ char sm[];
    const int tid  = threadIdx.x;
    const int wid  = tid >> 5;
    const int lane = tid & 31;
    const int bz    = blockIdx.z;
    const int rbase = blockIdx.y * 128;  // d0 rows
    const int cbase = blockIdx.x * 128;  // d1 rows

    // ---- load all four operand tiles into padded smem (16B chunks) ----
    {
        const uint4* gAh = reinterpret_cast<const uint4*>(g_ah + ((size_t)bz * N + rbase) * D);
        const uint4* gAl = reinterpret_cast<const uint4*>(g_al + ((size_t)bz * N + rbase) * D);
        const uint4* gBh = reinterpret_cast<const uint4*>(g_bh + ((size_t)bz * M + cbase) * D);
        const uint4* gBl = reinterpret_cast<const uint4*>(g_bl + ((size_t)bz * M + cbase) * D);
#pragma unroll
        for (int i = tid; i < 2048; i += 256) {  // 128 rows * 16 chunks
            int r = i >> 4, j = i & 15;
            size_t so = (size_t)r * ROWB + j * 16;
            *reinterpret_cast<uint4*>(sm + SA_H + so) = gAh[i];
            *reinterpret_cast<uint4*>(sm + SA_L + so) = gAl[i];
            *reinterpret_cast<uint4*>(sm + SB_H + so) = gBh[i];
            *reinterpret_cast<uint4*>(sm + SB_L + so) = gBl[i];
        }
    }
    __syncthreads();

    const uint32_t sb = smem_u32(sm);
    const int wm = (wid & 3) * 32;   // warp row offset in tile
    const int wn = (wid >> 2) * 64;  // warp col offset in tile

    // ldmatrix per-thread addressing components
    const int a_r  = ((lane >> 3) & 1) * 8 + (lane & 7);  // row within 16-row group
    const int a_cb = ((lane >> 4) & 1) * 16;              // k byte offset (k8 half)
    const int b_r  = ((lane >> 4) & 1) * 8 + (lane & 7);
    const int b_cb = ((lane >> 3) & 1) * 16;

    float acc[2][8][4];
#pragma unroll
    for (int mt = 0; mt < 2; ++mt)
#pragma unroll
        for (int nt = 0; nt < 8; ++nt)
#pragma unroll
            for (int q = 0; q < 4; ++q) acc[mt][nt][q] = 0.0f;

#pragma unroll
    for (int p = 0; p < 3; ++p) {  // (Ah,Bh), (Ah,Bl), (Al,Bh)
        const uint32_t Ab = sb + (p == 2 ? SA_L : SA_H);
        const uint32_t Bb = sb + (p == 1 ? SB_L : SB_H);
#pragma unroll
        for (int ks = 0; ks < 8; ++ks) {
            uint32_t a[2][4], b[4][4];
#pragma unroll
            for (int mt = 0; mt < 2; ++mt)
                ldmatrix_x4(a[mt], Ab + (uint32_t)(wm + mt * 16 + a_r) * ROWB + a_cb + ks * 32);
#pragma unroll
            for (int nt2 = 0; nt2 < 4; ++nt2)
                ldmatrix_x4(b[nt2], Bb + (uint32_t)(wn + nt2 * 16 + b_r) * ROWB + b_cb + ks * 32);
#pragma unroll
            for (int mt = 0; mt < 2; ++mt)
#pragma unroll
                for (int nt = 0; nt < 8; ++nt)
                    mma_16816(acc[mt][nt], a[mt], &b[nt >> 1][(nt & 1) * 2]);
        }
    }

    // ---- epilogue: direct float2 stores ----
    const int rr = rbase + wm + (lane >> 2);
    const int cc = cbase + wn + (lane & 3) * 2;
#pragma unroll
    for (int mt = 0; mt < 2; ++mt)
#pragma unroll
        for (int nt = 0; nt < 8; ++nt) {
            float* p = sim + ((size_t)bz * N + rr + mt * 16) * M + cc + nt * 8;
            *reinterpret_cast<float2*>(p) = make_float2(acc[mt][nt][0], acc[mt][nt][1]);
            *reinterpret_cast<float2*>(p + 8 * (size_t)M) =
                make_float2(acc[mt][nt][2], acc[mt][nt][3]);
        }
}

// ---------------------------------------------------------------------------
// Kernel 3: per-row top-2 over M, ratio/distance test -> g_m0
// ---------------------------------------------------------------------------
__global__ void row_top2_kernel(const float* __restrict__ sim) {
    int row = blockIdx.x;  // b*N + n
    const float* p = sim + (size_t)row * M;
    int tid = threadIdx.x;

    Top2 t; t2_init(t);
#pragma unroll 4
    for (int m = tid; m < M; m += 256) t2_push(t, p[m], m);

    __shared__ Top2 sh[256];
    sh[tid] = t;
    __syncthreads();
    for (int s = 128; s > 0; s >>= 1) {
        if (tid < s) t2_merge(sh[tid], sh[tid + s]);
        __syncthreads();
    }
    if (tid == 0) g_m0[row] = t2_match(sh[0]);
}

// ---------------------------------------------------------------------------
// Kernel 4a: per-column top-2 partials over N/NSPLIT rows
// ---------------------------------------------------------------------------
__global__ void col_top2_part_kernel(const float* __restrict__ sim) {
    int m = blockIdx.x * 256 + threadIdx.x;
    int s = blockIdx.y;
    int b = blockIdx.z;
    constexpr int RS = N / NSPLIT;  // 512
    int n0 = s * RS;
    const float* p = sim + ((size_t)b * N + n0) * M + m;

    Top2 t; t2_init(t);
#pragma unroll 4
    for (int r = 0; r < RS; ++r) t2_push(t, p[(size_t)r * M], n0 + r);

    g_colpart[((size_t)(b * NSPLIT + s)) * M + m] = t;
}

// ---------------------------------------------------------------------------
// Kernel 4b: merge column partials -> g_m1
// ---------------------------------------------------------------------------
__global__ void col_top2_merge_kernel() {
    int idx = blockIdx.x * 256 + threadIdx.x;  // b*M + m
    int b = idx / M, m = idx % M;

    Top2 t = g_colpart[(size_t)b * NSPLIT * M + m];
#pragma unroll
    for (int s = 1; s < NSPLIT; ++s)
        t2_merge(t, g_colpart[((size_t)b * NSPLIT + s) * M + m]);

    g_m1[idx] = t2_match(t);
}

// ---------------------------------------------------------------------------
// Kernel 5: mutual check + write matches/mscores
//   out layout: [matches0 | matches1 | mscores0 | mscores1 | sim]
// ---------------------------------------------------------------------------
__global__ void finalize_kernel(float* __restrict__ out) {
    int idx = blockIdx.x * 256 + threadIdx.x;  // b*N + n  (N == M)
    int b = idx / N, n = idx % N;

    int m0v = g_m0[idx];
    bool ok0 = (m0v > -1) && (g_m1[b * M + m0v] == n);
    out[idx]          = ok0 ? (float)m0v : -1.0f;
    out[2 * BN + idx] = ok0 ? 1.0f : 0.0f;

    int m1v = g_m1[idx];
    bool ok1 = (m1v > -1) && (g_m0[b * N + m1v] == n);
    out[BN + idx]     = ok1 ? (float)m1v : -1.0f;
    out[3 * BN + idx] = ok1 ? 1.0f : 0.0f;
}

// ---------------------------------------------------------------------------
// Launch
// ---------------------------------------------------------------------------
extern "C" void kernel_launch(void* const* d_in, const int* in_sizes, int n_in,
                              void* d_out, int out_size) {
    (void)in_sizes; (void)n_in; (void)out_size;
    const float* d0 = (const float*)d_in[0];
    const float* d1 = (const float*)d_in[1];
    float* out = (float*)d_out;
    float* sim = out + 4 * (size_t)BN;

    cudaFuncSetAttribute(sim_gemm_kernel,
                         cudaFuncAttributeMaxDynamicSharedMemorySize, SMEM_BYTES);

    norm_split_kernel<<<(B * N + B * M) / 8, 256>>>(d0, d1);
    sim_gemm_kernel<<<dim3(M / 128, N / 128, B), 256, SMEM_BYTES>>>(sim);
    row_top2_kernel<<<BN, 256>>>(sim);
    col_top2_part_kernel<<<dim3(M / 256, NSPLIT, B), 256>>>(sim);
    col_top2_merge_kernel<<<BN / 256, 256>>>();
    finalize_kernel<<<BN / 256, 256>>>(out);
}